// round 12
// baseline (speedup 1.0000x reference)
#include <cuda_runtime.h>
#include <cstdint>

#define THREADS 256
#define UNROLL  2
#define CHUNK   (THREADS * UNROLL)    // 512 float4 per block-iteration
#define BLOCKS  740                   // 5 resident blocks/SM * 148 SMs

// f = -W1^T( m1 .* W2^T( m2 .* g2 ) ) depends ONLY on the 12 relu-sign bits.
// flut[(m2n<<8)|m1n] = final (fx,fy), NEGATIVE-sign mask indexing.
// Weights live in SMEM (broadcast LDS, conflict-free) -> ~46 regs -> 40 warps/SM.
__global__ __launch_bounds__(THREADS, 5) void toy_force_kernel(
    const float4* __restrict__ pin,
    float4* __restrict__ pout,
    const float* __restrict__ W1,   // [8,2]
    const float* __restrict__ b1,   // [8]
    const float* __restrict__ W2,   // [4,8]
    const float* __restrict__ b2,   // [4]
    const float* __restrict__ W3,   // [2,4]
    int n_chunks)
{
    __shared__ __align__(16) float2 flut[4096];   // 32 KB
    __shared__ __align__(16) float4 w1r[8];       // (w1x, w1y, b1, 0) per neuron
    __shared__ __align__(16) float4 w2r[8];       // w2 row j = w2r[2j],w2r[2j+1]
    __shared__ __align__(16) float4 b2s;

    const int tid = threadIdx.x;
    int c = blockIdx.x;

    // ---- first-chunk loads issued immediately (hide prologue) ----
    float4 p0 = pin[c * CHUNK + tid];
    float4 p1 = pin[c * CHUNK + tid + THREADS];

    // ---- stage weights into smem ----
    if (tid < 8)
        w1r[tid] = make_float4(__ldg(&W1[2*tid]), __ldg(&W1[2*tid+1]),
                               __ldg(&b1[tid]), 0.0f);
    else if (tid < 16)
        w2r[tid - 8] = __ldg(&reinterpret_cast<const float4*>(W2)[tid - 8]);
    else if (tid == 16)
        b2s = __ldg(reinterpret_cast<const float4*>(b2));
    __syncthreads();

    // ---- build force LUT: thread owns m1n = tid; 16 m2n variants ----
    {
        const float4* v3 = reinterpret_cast<const float4*>(W3);
        float4 r0 = __ldg(&v3[0]), r1 = __ldg(&v3[1]);
        float ng2[4] = { -(r0.x + r1.x), -(r0.y + r1.y),
                         -(r0.z + r1.z), -(r0.w + r1.w) };
        int m1n = tid;                       // bit set = layer-1 neuron INACTIVE
        float cx[4], cy[4];
        #pragma unroll
        for (int j = 0; j < 4; j++) {
            const float* w2j = reinterpret_cast<const float*>(&w2r[2*j]);
            float ax = 0.0f, ay = 0.0f;
            #pragma unroll
            for (int i = 0; i < 8; i++) {
                float act = (float)(((m1n >> i) & 1) ^ 1);
                float w = w2j[i] * act;
                ax = fmaf(w, w1r[i].x, ax);
                ay = fmaf(w, w1r[i].y, ay);
            }
            cx[j] = ax * ng2[j];             // pre-scaled by -g2_j
            cy[j] = ay * ng2[j];
        }
        #pragma unroll
        for (int m2n = 0; m2n < 16; m2n++) {
            float fx = 0.0f, fy = 0.0f;
            #pragma unroll
            for (int j = 0; j < 4; j++)
                if (!(m2n & (1 << j))) { fx += cx[j]; fy += cy[j]; }
            flut[(m2n << 8) | m1n] = make_float2(fx, fy);   // conflict-free STS
        }
    }
    __syncthreads();

    while (true) {
        #pragma unroll
        for (int u = 0; u < UNROLL; u++) {
            float4 pv = (u == 0) ? p0 : p1;

            // ---- layer 1 for both samples, weights broadcast from smem ----
            float h1a[8], h1b[8];
            int ia = 0, ib = 0;
            #pragma unroll
            for (int i = 0; i < 8; i++) {
                float4 r = w1r[i];                       // LDS.128 broadcast
                float za = fmaf(r.x, pv.x, fmaf(r.y, pv.y, r.z));
                float zb = fmaf(r.x, pv.z, fmaf(r.y, pv.w, r.z));
                int sa = __float_as_int(za) >> 31;       // 0 or -1
                int sb = __float_as_int(zb) >> 31;
                ia |= sa & (1 << i);                     // LOP3
                ib |= sb & (1 << i);
                h1a[i] = __int_as_float(__float_as_int(za) & ~sa);  // relu
                h1b[i] = __int_as_float(__float_as_int(zb) & ~sb);
            }

            // ---- layer 2 signs, w2 rows broadcast from smem ----
            float4 bb = b2s;
            #pragma unroll
            for (int j = 0; j < 4; j++) {
                float4 lo = w2r[2*j];                    // w2[j][0..3]
                float4 hi = w2r[2*j + 1];                // w2[j][4..7]
                float bj = (j == 0) ? bb.x : (j == 1) ? bb.y : (j == 2) ? bb.z : bb.w;
                float za = bj, zb = bj;
                za = fmaf(lo.x, h1a[0], za); zb = fmaf(lo.x, h1b[0], zb);
                za = fmaf(lo.y, h1a[1], za); zb = fmaf(lo.y, h1b[1], zb);
                za = fmaf(lo.z, h1a[2], za); zb = fmaf(lo.z, h1b[2], zb);
                za = fmaf(lo.w, h1a[3], za); zb = fmaf(lo.w, h1b[3], zb);
                za = fmaf(hi.x, h1a[4], za); zb = fmaf(hi.x, h1b[4], zb);
                za = fmaf(hi.y, h1a[5], za); zb = fmaf(hi.y, h1b[5], zb);
                za = fmaf(hi.z, h1a[6], za); zb = fmaf(hi.z, h1b[6], zb);
                za = fmaf(hi.w, h1a[7], za); zb = fmaf(hi.w, h1b[7], zb);
                ia |= (__float_as_int(za) >> 31) & (256 << j);
                ib |= (__float_as_int(zb) >> 31) & (256 << j);
            }

            // ---- final force: two LDS.64 lookups ----
            float2 fa = flut[ia];
            float2 fb = flut[ib];
            pout[c * CHUNK + tid + u * THREADS] = make_float4(fa.x, fa.y, fb.x, fb.y);
        }

        c += BLOCKS;
        if (c >= n_chunks) break;
        p0 = pin[c * CHUNK + tid];
        p1 = pin[c * CHUNK + tid + THREADS];
    }
}

extern "C" void kernel_launch(void* const* d_in, const int* in_sizes, int n_in,
                              void* d_out, int out_size)
{
    const float4* pin = (const float4*)d_in[0];
    const float*  W1  = (const float*)d_in[1];
    const float*  b1  = (const float*)d_in[2];
    const float*  W2  = (const float*)d_in[3];
    const float*  b2  = (const float*)d_in[4];
    const float*  W3  = (const float*)d_in[5];
    float4* pout = (float4*)d_out;

    int n_floats = in_sizes[0];        // N*2
    int n_vec4   = n_floats / 4;       // 2,097,152 (divisible by CHUNK=512)
    int n_chunks = n_vec4 / CHUNK;     // 4096

    int blocks = BLOCKS < n_chunks ? BLOCKS : n_chunks;
    toy_force_kernel<<<blocks, THREADS>>>(pin, pout, W1, b1, W2, b2, W3, n_chunks);
}